// round 16
// baseline (speedup 1.0000x reference)
#include <cuda_runtime.h>
#include <cuda_bf16.h>
#include <cstdint>

#define TT 512
#define BB 64
#define II 256
#define HH 1024
#define OO 128
#define NCTA 128   // scan grid: 16 nt-groups x 8 k-splits

// ---------------- scratch (device globals; no allocation allowed) ----------------
static __device__ __nv_bfloat16 g_x0[TT * BB * II];   // x [T,B,I], bf16 hi
static __device__ __nv_bfloat16 g_x1[TT * BB * II];   // bf16 lo
static __device__ __nv_bfloat16 g_wih0[HH * II];
static __device__ __nv_bfloat16 g_wih1[HH * II];
static __device__ __nv_bfloat16 g_whh0[HH * HH];
static __device__ __nv_bfloat16 g_whh1[HH * HH];
static __device__ float         g_xp[(size_t)TT * BB * HH];  // [t][j][b]  (transposed)
static __device__ float         g_part[2 * 8 * BB * HH];     // [parity][ks][j][b]
// h buffers: [buf(3)][j-block(8)][SW128-swizzled 16KB block]
static __device__ __nv_bfloat16 g_h0[3 * BB * HH];
static __device__ __nv_bfloat16 g_h1[3 * BB * HH];
static __device__ float         g_hT[BB * HH];               // h_512, [b][j] for final linear
static __device__ unsigned      g_flagA[NCTA * 8];           // per-WARP partial flags [cta][warp]
static __device__ unsigned      g_flagB[NCTA * 8];           // h-slice-ready (32B padded)

// ---------------- helpers ----------------
__device__ __forceinline__ unsigned ld_acq(const unsigned* p) {
    unsigned v;
    asm volatile("ld.acquire.gpu.u32 %0, [%1];" : "=r"(v) : "l"(p) : "memory");
    return v;
}
__device__ __forceinline__ void st_rel(unsigned* p, unsigned v) {
    asm volatile("st.release.gpu.u32 [%0], %1;" ::"l"(p), "r"(v) : "memory");
}

__device__ __forceinline__ uint32_t smem_u32(const void* p) {
    uint32_t a;
    asm("{ .reg .u64 t; cvta.to.shared.u64 t, %1; cvt.u32.u64 %0, t; }" : "=r"(a) : "l"(p));
    return a;
}

__device__ __forceinline__ void mbar_wait(uint32_t mbar, uint32_t parity) {
    asm volatile(
        "{\n\t.reg .pred P;\n\tWL%=:\n\t"
        "mbarrier.try_wait.parity.shared.b64 P, [%0], %1;\n\t"
        "@P bra.uni WD%=;\n\tbra.uni WL%=;\n\tWD%=:\n\t}"
        ::"r"(mbar), "r"(parity) : "memory");
}

__device__ __forceinline__ float ftanh(float x) {
    float xx = fminf(fmaxf(x, -15.0f), 15.0f);
    float e = __expf(2.0f * xx);
    return __fdividef(e - 1.0f, e + 1.0f);
}

__device__ __forceinline__ void mma16816(float& d0, float& d1, float& d2, float& d3,
                                         unsigned a0, unsigned a1, unsigned a2, unsigned a3,
                                         unsigned b0, unsigned b1) {
    asm volatile(
        "mma.sync.aligned.m16n8k16.row.col.f32.bf16.bf16.f32 "
        "{%0,%1,%2,%3},{%4,%5,%6,%7},{%8,%9},{%0,%1,%2,%3};\n"
        : "+f"(d0), "+f"(d1), "+f"(d2), "+f"(d3)
        : "r"(a0), "r"(a1), "r"(a2), "r"(a3), "r"(b0), "r"(b1));
}

__device__ __forceinline__ void ldsm_x4(unsigned& r0, unsigned& r1, unsigned& r2, unsigned& r3,
                                        uint32_t addr) {
    asm volatile("ldmatrix.sync.aligned.m8n8.x4.shared.b16 {%0,%1,%2,%3}, [%4];"
                 : "=r"(r0), "=r"(r1), "=r"(r2), "=r"(r3) : "r"(addr));
}
__device__ __forceinline__ void ldsm_x4t(unsigned& r0, unsigned& r1, unsigned& r2, unsigned& r3,
                                         uint32_t addr) {
    asm volatile("ldmatrix.sync.aligned.m8n8.x4.trans.shared.b16 {%0,%1,%2,%3}, [%4];"
                 : "=r"(r0), "=r"(r1), "=r"(r2), "=r"(r3) : "r"(addr));
}

__device__ __forceinline__ void cp16(uint32_t dst, const void* src) {
    asm volatile("cp.async.ca.shared.global [%0], [%1], 16;" ::"r"(dst), "l"(src) : "memory");
}

template <int COLS, int PAD>
__device__ __forceinline__ void copy_tile(__nv_bfloat16* dst, const __nv_bfloat16* src,
                                          int src_stride) {
    constexpr int U4R = COLS / 8;
    constexpr int TOT = 64 * U4R;
#pragma unroll 4
    for (int it = threadIdx.x; it < TOT; it += 256) {
        int r = it / U4R;
        int c = (it % U4R) * 8;
        *reinterpret_cast<uint4*>(dst + r * PAD + c) =
            *reinterpret_cast<const uint4*>(src + r * src_stride + c);
    }
}

// ---------------- fused prep: splits + h init + flags (one launch) ----------------
__global__ void fused_prep_kernel(const float* __restrict__ x,
                                  const float* __restrict__ W_ih,
                                  const float* __restrict__ W_hh) {
    int blk = blockIdx.x;
    if (blk < 32768) {
        int i = blk * 256 + threadIdx.x;
        int ii = i & (II - 1);
        int tb = i >> 8;
        int b = tb & (BB - 1);
        int t = tb >> 6;
        float v = x[((size_t)(b * TT + t) << 8) + ii];
        __nv_bfloat16 h = __float2bfloat16(v);
        g_x0[i] = h;
        g_x1[i] = __float2bfloat16(v - __bfloat162float(h));
    } else if (blk < 36864) {
        int i = (blk - 32768) * 256 + threadIdx.x;
        float v = W_hh[i];
        __nv_bfloat16 h = __float2bfloat16(v);
        g_whh0[i] = h;
        g_whh1[i] = __float2bfloat16(v - __bfloat162float(h));
    } else if (blk < 37888) {
        int i = (blk - 36864) * 256 + threadIdx.x;
        float v = W_ih[i];
        __nv_bfloat16 h = __float2bfloat16(v);
        g_wih0[i] = h;
        g_wih1[i] = __float2bfloat16(v - __bfloat162float(h));
    } else {
        int i = (blk - 37888) * 256 + threadIdx.x;
        __nv_bfloat16 z = __float2bfloat16(0.0f);
        g_h0[i] = z;   // buffer 0 = h_0 (zeros are swizzle-invariant; re-zeroed every replay)
        g_h1[i] = z;
        if (i < NCTA * 8) {
            g_flagA[i] = 0u;
            g_flagB[i] = 0u;
        }
    }
}

// no-op spacer so rnn_scan is the 4th launch (ncu captures launch #4)
__global__ void spacer_kernel() {}

// ---------------- phase 1: xp[t][j][b] = (x @ W_ih^T + b_ih + b_hh)^T ----------------
// R12 tiling; tile loads via cp.async (R15 version, kept).
__global__ void __launch_bounds__(256, 1)
xp_gemm_kernel(const float* __restrict__ b_ih, const float* __restrict__ b_hh) {
    extern __shared__ __align__(16) unsigned char smem_raw[];
    __nv_bfloat16* sx0 = reinterpret_cast<__nv_bfloat16*>(smem_raw);
    __nv_bfloat16* sx1 = sx0 + 64 * 264;
    __nv_bfloat16* sw0 = sx1 + 64 * 264;
    __nv_bfloat16* sw1 = sw0 + 64 * 264;

    const int mt = blockIdx.x;   // = t (64 batch rows)
    const int nt = blockIdx.y;   // hidden tile
    const int tid = threadIdx.x;

    // async tile loads: 4 tiles x 64 rows x 32 chunks of 16B, PAD row = 528B
    {
        const uint32_t ux0 = smem_u32(sx0), ux1 = smem_u32(sx1);
        const uint32_t uw0 = smem_u32(sw0), uw1 = smem_u32(sw1);
        const __nv_bfloat16* gx0 = g_x0 + (size_t)(mt * 64) * II;
        const __nv_bfloat16* gx1 = g_x1 + (size_t)(mt * 64) * II;
        const __nv_bfloat16* gw0 = g_wih0 + (size_t)(nt * 64) * II;
        const __nv_bfloat16* gw1 = g_wih1 + (size_t)(nt * 64) * II;
#pragma unroll
        for (int i = 0; i < 8; ++i) {
            int e = tid + i * 256;           // 0..2047
            int r = e >> 5;
            int c = (e & 31) * 8;            // element column
            uint32_t off = (uint32_t)(r * 528 + c * 2);
            cp16(ux0 + off, gx0 + (size_t)r * II + c);
            cp16(ux1 + off, gx1 + (size_t)r * II + c);
            cp16(uw0 + off, gw0 + (size_t)r * II + c);
            cp16(uw1 + off, gw1 + (size_t)r * II + c);
        }
        asm volatile("cp.async.commit_group;" ::: "memory");
        asm volatile("cp.async.wait_group 0;" ::: "memory");
    }
    __syncthreads();

    const int warp = tid >> 5, lane = tid & 31;
    const int m0 = (warp >> 1) << 4;
    const int n0 = (warp & 1) << 5;
    const int gr = lane >> 2;
    const int qc = (lane & 3) << 1;

    float d[4][4] = {};
#pragma unroll
    for (int seg = 0; seg < 3; ++seg) {
        const __nv_bfloat16* A = (seg < 2) ? sx0 : sx1;
        const __nv_bfloat16* Bm = (seg == 1) ? sw1 : sw0;
        const __nv_bfloat16* ar = A + (m0 + gr) * 264 + qc;
#pragma unroll 4
        for (int kk = 0; kk < 256; kk += 16) {
            unsigned a0 = *reinterpret_cast<const unsigned*>(ar + kk);
            unsigned a1 = *reinterpret_cast<const unsigned*>(ar + kk + 8 * 264);
            unsigned a2 = *reinterpret_cast<const unsigned*>(ar + kk + 8);
            unsigned a3 = *reinterpret_cast<const unsigned*>(ar + kk + 8 * 264 + 8);
#pragma unroll
            for (int nj = 0; nj < 4; ++nj) {
                const __nv_bfloat16* bp = Bm + (n0 + nj * 8 + gr) * 264 + kk + qc;
                unsigned b0 = *reinterpret_cast<const unsigned*>(bp);
                unsigned b1 = *reinterpret_cast<const unsigned*>(bp + 8);
                mma16816(d[nj][0], d[nj][1], d[nj][2], d[nj][3], a0, a1, a2, a3, b0, b1);
            }
        }
    }

    // transposed store: xp[t=mt][j][b]
    const int bb = m0 + gr;
    const int colg = nt * 64 + n0 + qc;
    float* outb = g_xp + (size_t)mt * (BB * HH);
#pragma unroll
    for (int nj = 0; nj < 4; ++nj) {
        int j = colg + nj * 8;
        float bsA = b_ih[j] + b_hh[j];
        float bsB = b_ih[j + 1] + b_hh[j + 1];
        outb[(size_t)j * 64 + bb] = d[nj][0] + bsA;
        outb[(size_t)(j + 1) * 64 + bb] = d[nj][1] + bsB;
        outb[(size_t)j * 64 + bb + 8] = d[nj][2] + bsA;
        outb[(size_t)(j + 1) * 64 + bb + 8] = d[nj][3] + bsB;
    }
}

// ---------------- phase 2: persistent scan, role-split + per-warp fA flags ----------------
// fA is published per WARP right after that warp's partial stores (syncwarp + release),
// so reducers wait only on the 2 producing warps per CTA, not the block barrier.
__global__ void __launch_bounds__(256, 1) rnn_scan_kernel() {
    extern __shared__ __align__(16) unsigned char smem_raw[];
    const uint32_t sbase = smem_u32(smem_raw);
    const uint32_t uSH0 = sbase;            // 16KB swizzled h0 k-window
    const uint32_t uSH1 = sbase + 16384;    // 16KB swizzled h1 k-window
    __nv_bfloat16* sw0 = reinterpret_cast<__nv_bfloat16*>(smem_raw + 32768);   // 64 x 136
    __nv_bfloat16* sw1 = sw0 + 64 * 136;
    const uint32_t mbF = sbase + 67584;     // 4 quarter barriers

    const int tid = threadIdx.x;
    const int bid = blockIdx.x;
    const int nt = bid >> 3;
    const int ks = bid & 7;

    copy_tile<128, 136>(sw0, g_whh0 + (size_t)(nt * 64) * HH + ks * 128, HH);
    copy_tile<128, 136>(sw1, g_whh1 + (size_t)(nt * 64) * HH + ks * 128, HH);
    if (tid == 0) {
#pragma unroll
        for (int i = 0; i < 4; ++i)
            asm volatile("mbarrier.init.shared.b64 [%0], %1;"
                         ::"r"(mbF + i * 8), "r"(1u) : "memory");
    }
    __syncthreads();

    const int warp = tid >> 5, lane = tid & 31;
    const int m0 = (warp >> 1) << 4;   // j sub-tile
    const int n0 = (warp & 1) << 5;    // b half
    const int gr = lane >> 2;
    const int qc = (lane & 3) << 1;

    // hoist W fragments into registers for all 512 steps
    const uint32_t uW0 = smem_u32(sw0), uW1 = smem_u32(sw1);
    const uint32_t a_off = (uint32_t)((m0 + (lane & 15)) * 272 + (lane >> 4) * 16);
    unsigned W0f[8][4], W1f[8][4];
#pragma unroll
    for (int kk = 0; kk < 8; ++kk) {
        ldsm_x4(W0f[kk][0], W0f[kk][1], W0f[kk][2], W0f[kk][3], uW0 + a_off + kk * 32);
        ldsm_x4(W1f[kk][0], W1f[kk][1], W1f[kk][2], W1f[kk][3], uW1 + a_off + kk * 32);
    }

    // swizzled ldsm bases for h tiles (128B rows, SW128 XOR; constant per lane)
    const uint32_t raw1 = (uint32_t)((lane & 15) * 128 + (((lane >> 4) << 3) + n0) * 2);
    const uint32_t raw2 = raw1 + 32;
    const uint32_t hA = raw1 ^ ((raw1 >> 3) & 0x70);
    const uint32_t hB = raw2 ^ ((raw2 >> 3) & 0x70);

    unsigned* const fA_my = g_flagA + bid * 8 + warp;   // per-warp flag slot
    unsigned* const fB_my = g_flagB + bid * 8;
    const unsigned* const fBq =
        g_flagB + (size_t)(ks * 16 + (warp & 3) * 4 + (lane & 3)) * 8;
    // reducer (warp 4, lanes 0-15): 8 producer CTAs x 2 warps ((bid&6)+{0,1})
    const unsigned* const fAp =
        g_flagA + (size_t)(nt * 8 + (lane >> 1)) * 8 + (bid & 6) + (lane & 1);
    const int rbase = bid * 512 + (tid & 127) * 4;   // reduce slice (warps 4-7)

    // ---- prologue: issue DMA for step 0 (flags trivially 0) ----
    if (warp < 4) {
        if (lane < 4) {
            while (ld_acq(fBq) != 0u) {}
        }
        __syncwarp();
        if (lane == 0) {
            const uint32_t mb = mbF + warp * 8;
            const uint32_t off = (uint32_t)(warp * 4096);
            const char* s0 = reinterpret_cast<const char*>(g_h0) + ks * 16384 + off;
            const char* s1 = reinterpret_cast<const char*>(g_h1) + ks * 16384 + off;
            asm volatile("mbarrier.arrive.expect_tx.shared.b64 _, [%0], %1;"
                         ::"r"(mb), "r"(8192u) : "memory");
            asm volatile(
                "cp.async.bulk.shared::cluster.global.mbarrier::complete_tx::bytes "
                "[%0], [%1], %2, [%3];"
                ::"r"(uSH0 + off), "l"(s0), "r"(4096u), "r"(mb) : "memory");
            asm volatile(
                "cp.async.bulk.shared::cluster.global.mbarrier::complete_tx::bytes "
                "[%0], [%1], %2, [%3];"
                ::"r"(uSH1 + off), "l"(s1), "r"(4096u), "r"(mb) : "memory");
        }
    }

    for (int t = 0; t < TT; ++t) {
        const unsigned p = (unsigned)(t & 1);

        // xp prefetch for reduce (warps 4-7; hidden behind MMA)
        float4 acc = make_float4(0.f, 0.f, 0.f, 0.f);
        if (warp >= 4)
            acc = *reinterpret_cast<const float4*>(g_xp + (size_t)t * (BB * HH) + rbase);

        // ---- MMA with progressive quarter waits: D += W0*h0 + W1*h0 + W0*h1 ----
        float d[4][4] = {};
#pragma unroll
        for (int kk = 0; kk < 8; ++kk) {
            if ((kk & 1) == 0) mbar_wait(mbF + (kk >> 1) * 8, p);
            unsigned r0, r1, r2, r3, s0, s1, s2, s3;
            ldsm_x4t(r0, r1, r2, r3, uSH0 + hA + kk * 2048);
            ldsm_x4t(s0, s1, s2, s3, uSH0 + hB + kk * 2048);
            mma16816(d[0][0], d[0][1], d[0][2], d[0][3],
                     W0f[kk][0], W0f[kk][1], W0f[kk][2], W0f[kk][3], r0, r1);
            mma16816(d[1][0], d[1][1], d[1][2], d[1][3],
                     W0f[kk][0], W0f[kk][1], W0f[kk][2], W0f[kk][3], r2, r3);
            mma16816(d[2][0], d[2][1], d[2][2], d[2][3],
                     W0f[kk][0], W0f[kk][1], W0f[kk][2], W0f[kk][3], s0, s1);
            mma16816(d[3][0], d[3][1], d[3][2], d[3][3],
                     W0f[kk][0], W0f[kk][1], W0f[kk][2], W0f[kk][3], s2, s3);
            mma16816(d[0][0], d[0][1], d[0][2], d[0][3],
                     W1f[kk][0], W1f[kk][1], W1f[kk][2], W1f[kk][3], r0, r1);
            mma16816(d[1][0], d[1][1], d[1][2], d[1][3],
                     W1f[kk][0], W1f[kk][1], W1f[kk][2], W1f[kk][3], r2, r3);
            mma16816(d[2][0], d[2][1], d[2][2], d[2][3],
                     W1f[kk][0], W1f[kk][1], W1f[kk][2], W1f[kk][3], s0, s1);
            mma16816(d[3][0], d[3][1], d[3][2], d[3][3],
                     W1f[kk][0], W1f[kk][1], W1f[kk][2], W1f[kk][3], s2, s3);
            unsigned u0, u1, u2, u3, v0, v1, v2, v3;
            ldsm_x4t(u0, u1, u2, u3, uSH1 + hA + kk * 2048);
            ldsm_x4t(v0, v1, v2, v3, uSH1 + hB + kk * 2048);
            mma16816(d[0][0], d[0][1], d[0][2], d[0][3],
                     W0f[kk][0], W0f[kk][1], W0f[kk][2], W0f[kk][3], u0, u1);
            mma16816(d[1][0], d[1][1], d[1][2], d[1][3],
                     W0f[kk][0], W0f[kk][1], W0f[kk][2], W0f[kk][3], u2, u3);
            mma16816(d[2][0], d[2][1], d[2][2], d[2][3],
                     W0f[kk][0], W0f[kk][1], W0f[kk][2], W0f[kk][3], v0, v1);
            mma16816(d[3][0], d[3][1], d[3][2], d[3][3],
                     W0f[kk][0], W0f[kk][1], W0f[kk][2], W0f[kk][3], v2, v3);
        }

        // ---- store partials [parity][ks][j][b]; publish THIS warp's tile immediately ----
        float* Pp = g_part + ((size_t)p * 8 + ks) * (BB * HH) +
                    (size_t)(nt * 64 + m0 + gr) * 64 + n0 + qc;
#pragma unroll
        for (int nj = 0; nj < 4; ++nj) {
            *reinterpret_cast<float2*>(Pp + nj * 8) = make_float2(d[nj][0], d[nj][1]);
            *reinterpret_cast<float2*>(Pp + nj * 8 + 8 * 64) = make_float2(d[nj][2], d[nj][3]);
        }
        __syncwarp();                       // intra-warp memory ordering for the release below
        if (lane == 0) st_rel(fA_my, p ^ 1u);
        __syncthreads();                    // all ldsm reads done before DMA overwrites sh

        if (warp < 4) {
            // ---- warps 0-3: poll next step's fB quarter + issue DMA (overlaps reduce) ----
            if (t < TT - 1) {
                const unsigned pn = (unsigned)((t + 1) & 1);
                if (lane < 4) {
                    while (ld_acq(fBq) != pn) {}
                }
                __syncwarp();
                if (lane == 0) {
                    const uint32_t mb = mbF + warp * 8;
                    const uint32_t off = (uint32_t)(warp * 4096);
                    const int tb = (t + 1) % 3;
                    const char* s0 =
                        reinterpret_cast<const char*>(g_h0) + tb * 131072 + ks * 16384 + off;
                    const char* s1 =
                        reinterpret_cast<const char*>(g_h1) + tb * 131072 + ks * 16384 + off;
                    asm volatile("mbarrier.arrive.expect_tx.shared.b64 _, [%0], %1;"
                                 ::"r"(mb), "r"(8192u) : "memory");
                    asm volatile(
                        "cp.async.bulk.shared::cluster.global.mbarrier::complete_tx::bytes "
                        "[%0], [%1], %2, [%3];"
                        ::"r"(uSH0 + off), "l"(s0), "r"(4096u), "r"(mb) : "memory");
                    asm volatile(
                        "cp.async.bulk.shared::cluster.global.mbarrier::complete_tx::bytes "
                        "[%0], [%1], %2, [%3];"
                        ::"r"(uSH1 + off), "l"(s1), "r"(4096u), "r"(mb) : "memory");
                }
            }
        } else {
            // ---- warps 4-7: wait only the 16 producing-warp flags, reduce, publish fB ----
            if (warp == 4 && lane < 16) {
                while (ld_acq(fAp) != (p ^ 1u)) {}
            }
            asm volatile("bar.sync 2, 128;" ::: "memory");
            {
                float v[4] = {acc.x, acc.y, acc.z, acc.w};
#pragma unroll
                for (int s = 0; s < 8; ++s) {
                    float4 q = *reinterpret_cast<const float4*>(
                        g_part + ((size_t)p * 8 + s) * (BB * HH) + rbase);
                    v[0] += q.x; v[1] += q.y; v[2] += q.z; v[3] += q.w;
                }
#pragma unroll
                for (int i = 0; i < 4; ++i) v[i] = ftanh(v[i]);

                const int j = rbase >> 6, b0 = rbase & 63;
                uint32_t raw = (uint32_t)((j & 127) * 128 + b0 * 2);
                uint32_t boff = (uint32_t)(((t + 1) % 3) * 131072 + (j >> 7) * 16384) +
                                (raw ^ ((raw >> 3) & 0x70));
                __nv_bfloat162 h01, h23, l01, l23;
                h01.x = __float2bfloat16(v[0]);
                h01.y = __float2bfloat16(v[1]);
                h23.x = __float2bfloat16(v[2]);
                h23.y = __float2bfloat16(v[3]);
                l01.x = __float2bfloat16(v[0] - __bfloat162float(h01.x));
                l01.y = __float2bfloat16(v[1] - __bfloat162float(h01.y));
                l23.x = __float2bfloat16(v[2] - __bfloat162float(h23.x));
                l23.y = __float2bfloat16(v[3] - __bfloat162float(h23.y));
                *reinterpret_cast<__nv_bfloat162*>(reinterpret_cast<char*>(g_h0) + boff) = h01;
                *reinterpret_cast<__nv_bfloat162*>(reinterpret_cast<char*>(g_h0) + boff + 4) = h23;
                *reinterpret_cast<__nv_bfloat162*>(reinterpret_cast<char*>(g_h1) + boff) = l01;
                *reinterpret_cast<__nv_bfloat162*>(reinterpret_cast<char*>(g_h1) + boff + 4) = l23;
                if (t == TT - 1) {   // h_512 transposed [b][j] in f32
#pragma unroll
                    for (int i = 0; i < 4; ++i) g_hT[(size_t)(b0 + i) * HH + j] = v[i];
                }
            }
            asm volatile("bar.sync 2, 128;" ::: "memory");
            if (tid == 128) st_rel(fB_my, p ^ 1u);
        }
    }
}

// ---------------- phase 3: out = h_last @ W_lin^T + b_lin ----------------
__global__ void final_linear_kernel(const float* __restrict__ wlin,
                                    const float* __restrict__ blin,
                                    float* __restrict__ out) {
    int gw = (blockIdx.x * 256 + threadIdx.x) >> 5;
    int lane = threadIdx.x & 31;
    int b = gw >> 7;
    int o = gw & (OO - 1);
    const float* wr = wlin + (size_t)o * HH;
    const float* hr = g_hT + (size_t)b * HH;
    float sum = 0.0f;
#pragma unroll 8
    for (int k = lane; k < HH; k += 32) sum += hr[k] * wr[k];
#pragma unroll
    for (int off = 16; off > 0; off >>= 1) sum += __shfl_down_sync(0xffffffffu, sum, off);
    if (lane == 0) out[b * OO + o] = sum + blin[o];
}

// ---------------- launch ----------------
extern "C" void kernel_launch(void* const* d_in, const int* in_sizes, int n_in,
                              void* d_out, int out_size) {
    (void)in_sizes; (void)n_in; (void)out_size;
    const float* x     = (const float*)d_in[0];
    const float* W_ih  = (const float*)d_in[1];
    const float* W_hh  = (const float*)d_in[2];
    const float* b_ih  = (const float*)d_in[3];
    const float* b_hh  = (const float*)d_in[4];
    const float* W_lin = (const float*)d_in[5];
    const float* b_lin = (const float*)d_in[6];
    float* out = (float*)d_out;

    const int scan_smem = 67616;   // 32KB h + 34816B W + 4 mbarriers
    cudaFuncSetAttribute(xp_gemm_kernel, cudaFuncAttributeMaxDynamicSharedMemorySize,
                         4 * 64 * 264 * 2);
    cudaFuncSetAttribute(rnn_scan_kernel, cudaFuncAttributeMaxDynamicSharedMemorySize,
                         scan_smem);

    fused_prep_kernel<<<38144, 256>>>(x, W_ih, W_hh);                     // launch 1
    xp_gemm_kernel<<<dim3(512, 16), 256, 4 * 64 * 264 * 2>>>(b_ih, b_hh); // launch 2
    spacer_kernel<<<1, 32>>>();                                           // launch 3
    rnn_scan_kernel<<<NCTA, 256, scan_smem>>>();                          // launch 4 (ncu target)
    final_linear_kernel<<<(BB * OO * 32) / 256, 256>>>(W_lin, b_lin, out);
}

// round 17
// speedup vs baseline: 1.0954x; 1.0954x over previous
#include <cuda_runtime.h>
#include <cuda_bf16.h>
#include <cstdint>

#define TT 512
#define BB 64
#define II 256
#define HH 1024
#define OO 128
#define NCTA 128   // scan grid: 16 nt-groups x 8 k-splits

// ---------------- scratch (device globals; no allocation allowed) ----------------
static __device__ __nv_bfloat16 g_x0[TT * BB * II];   // x [T,B,I], bf16 hi
static __device__ __nv_bfloat16 g_x1[TT * BB * II];   // bf16 lo
static __device__ __nv_bfloat16 g_wih0[HH * II];
static __device__ __nv_bfloat16 g_wih1[HH * II];
static __device__ __nv_bfloat16 g_whh0[HH * HH];
static __device__ __nv_bfloat16 g_whh1[HH * HH];
static __device__ float         g_xp[(size_t)TT * BB * HH];  // [t][j][b]  (transposed)
static __device__ float         g_part[2 * 8 * BB * HH];     // [parity][ks][j][b]
// h buffers: [buf(3)][j-block(8)][SW128-swizzled 16KB block]
static __device__ __nv_bfloat16 g_h0[3 * BB * HH];
static __device__ __nv_bfloat16 g_h1[3 * BB * HH];
static __device__ float         g_hT[BB * HH];               // h_512, [b][j] for final linear
static __device__ unsigned      g_flagA[NCTA * 8];           // partials-ready (32B padded)
static __device__ unsigned      g_flagB[NCTA * 8];           // h-slice-ready

// ---------------- helpers ----------------
__device__ __forceinline__ unsigned ld_acq(const unsigned* p) {
    unsigned v;
    asm volatile("ld.acquire.gpu.u32 %0, [%1];" : "=r"(v) : "l"(p) : "memory");
    return v;
}
__device__ __forceinline__ void st_rel(unsigned* p, unsigned v) {
    asm volatile("st.release.gpu.u32 [%0], %1;" ::"l"(p), "r"(v) : "memory");
}

__device__ __forceinline__ uint32_t smem_u32(const void* p) {
    uint32_t a;
    asm("{ .reg .u64 t; cvta.to.shared.u64 t, %1; cvt.u32.u64 %0, t; }" : "=r"(a) : "l"(p));
    return a;
}

__device__ __forceinline__ void mbar_wait(uint32_t mbar, uint32_t parity) {
    asm volatile(
        "{\n\t.reg .pred P;\n\tWL%=:\n\t"
        "mbarrier.try_wait.parity.shared.b64 P, [%0], %1;\n\t"
        "@P bra.uni WD%=;\n\tbra.uni WL%=;\n\tWD%=:\n\t}"
        ::"r"(mbar), "r"(parity) : "memory");
}

__device__ __forceinline__ float ftanh(float x) {
    float xx = fminf(fmaxf(x, -15.0f), 15.0f);
    float e = __expf(2.0f * xx);
    return __fdividef(e - 1.0f, e + 1.0f);
}

__device__ __forceinline__ void mma16816(float& d0, float& d1, float& d2, float& d3,
                                         unsigned a0, unsigned a1, unsigned a2, unsigned a3,
                                         unsigned b0, unsigned b1) {
    asm volatile(
        "mma.sync.aligned.m16n8k16.row.col.f32.bf16.bf16.f32 "
        "{%0,%1,%2,%3},{%4,%5,%6,%7},{%8,%9},{%0,%1,%2,%3};\n"
        : "+f"(d0), "+f"(d1), "+f"(d2), "+f"(d3)
        : "r"(a0), "r"(a1), "r"(a2), "r"(a3), "r"(b0), "r"(b1));
}

__device__ __forceinline__ void ldsm_x4(unsigned& r0, unsigned& r1, unsigned& r2, unsigned& r3,
                                        uint32_t addr) {
    asm volatile("ldmatrix.sync.aligned.m8n8.x4.shared.b16 {%0,%1,%2,%3}, [%4];"
                 : "=r"(r0), "=r"(r1), "=r"(r2), "=r"(r3) : "r"(addr));
}
__device__ __forceinline__ void ldsm_x4t(unsigned& r0, unsigned& r1, unsigned& r2, unsigned& r3,
                                         uint32_t addr) {
    asm volatile("ldmatrix.sync.aligned.m8n8.x4.trans.shared.b16 {%0,%1,%2,%3}, [%4];"
                 : "=r"(r0), "=r"(r1), "=r"(r2), "=r"(r3) : "r"(addr));
}

__device__ __forceinline__ void cp16(uint32_t dst, const void* src) {
    asm volatile("cp.async.ca.shared.global [%0], [%1], 16;" ::"r"(dst), "l"(src) : "memory");
}

template <int COLS, int PAD>
__device__ __forceinline__ void copy_tile(__nv_bfloat16* dst, const __nv_bfloat16* src,
                                          int src_stride) {
    constexpr int U4R = COLS / 8;
    constexpr int TOT = 64 * U4R;
#pragma unroll 4
    for (int it = threadIdx.x; it < TOT; it += 256) {
        int r = it / U4R;
        int c = (it % U4R) * 8;
        *reinterpret_cast<uint4*>(dst + r * PAD + c) =
            *reinterpret_cast<const uint4*>(src + r * src_stride + c);
    }
}

// ---------------- fused prep: splits + h init + flags (one launch) ----------------
__global__ void fused_prep_kernel(const float* __restrict__ x,
                                  const float* __restrict__ W_ih,
                                  const float* __restrict__ W_hh) {
    int blk = blockIdx.x;
    if (blk < 32768) {
        int i = blk * 256 + threadIdx.x;
        int ii = i & (II - 1);
        int tb = i >> 8;
        int b = tb & (BB - 1);
        int t = tb >> 6;
        float v = x[((size_t)(b * TT + t) << 8) + ii];
        __nv_bfloat16 h = __float2bfloat16(v);
        g_x0[i] = h;
        g_x1[i] = __float2bfloat16(v - __bfloat162float(h));
    } else if (blk < 36864) {
        int i = (blk - 32768) * 256 + threadIdx.x;
        float v = W_hh[i];
        __nv_bfloat16 h = __float2bfloat16(v);
        g_whh0[i] = h;
        g_whh1[i] = __float2bfloat16(v - __bfloat162float(h));
    } else if (blk < 37888) {
        int i = (blk - 36864) * 256 + threadIdx.x;
        float v = W_ih[i];
        __nv_bfloat16 h = __float2bfloat16(v);
        g_wih0[i] = h;
        g_wih1[i] = __float2bfloat16(v - __bfloat162float(h));
    } else {
        int i = (blk - 37888) * 256 + threadIdx.x;
        __nv_bfloat16 z = __float2bfloat16(0.0f);
        g_h0[i] = z;   // buffer 0 = h_0 (zeros are swizzle-invariant; re-zeroed every replay)
        g_h1[i] = z;
        if (i < NCTA * 8) {
            g_flagA[i] = 0u;
            g_flagB[i] = 0u;
        }
    }
}

// no-op spacer so rnn_scan is the 4th launch (ncu captures launch #4)
__global__ void spacer_kernel() {}

// ---------------- phase 1: xp[t][j][b] = (x @ W_ih^T + b_ih + b_hh)^T ----------------
// R12 tiling; tile loads via cp.async (R15 version, kept).
__global__ void __launch_bounds__(256, 1)
xp_gemm_kernel(const float* __restrict__ b_ih, const float* __restrict__ b_hh) {
    extern __shared__ __align__(16) unsigned char smem_raw[];
    __nv_bfloat16* sx0 = reinterpret_cast<__nv_bfloat16*>(smem_raw);
    __nv_bfloat16* sx1 = sx0 + 64 * 264;
    __nv_bfloat16* sw0 = sx1 + 64 * 264;
    __nv_bfloat16* sw1 = sw0 + 64 * 264;

    const int mt = blockIdx.x;   // = t (64 batch rows)
    const int nt = blockIdx.y;   // hidden tile
    const int tid = threadIdx.x;

    // async tile loads: 4 tiles x 64 rows x 32 chunks of 16B, PAD row = 528B
    {
        const uint32_t ux0 = smem_u32(sx0), ux1 = smem_u32(sx1);
        const uint32_t uw0 = smem_u32(sw0), uw1 = smem_u32(sw1);
        const __nv_bfloat16* gx0 = g_x0 + (size_t)(mt * 64) * II;
        const __nv_bfloat16* gx1 = g_x1 + (size_t)(mt * 64) * II;
        const __nv_bfloat16* gw0 = g_wih0 + (size_t)(nt * 64) * II;
        const __nv_bfloat16* gw1 = g_wih1 + (size_t)(nt * 64) * II;
#pragma unroll
        for (int i = 0; i < 8; ++i) {
            int e = tid + i * 256;           // 0..2047
            int r = e >> 5;
            int c = (e & 31) * 8;            // element column
            uint32_t off = (uint32_t)(r * 528 + c * 2);
            cp16(ux0 + off, gx0 + (size_t)r * II + c);
            cp16(ux1 + off, gx1 + (size_t)r * II + c);
            cp16(uw0 + off, gw0 + (size_t)r * II + c);
            cp16(uw1 + off, gw1 + (size_t)r * II + c);
        }
        asm volatile("cp.async.commit_group;" ::: "memory");
        asm volatile("cp.async.wait_group 0;" ::: "memory");
    }
    __syncthreads();

    const int warp = tid >> 5, lane = tid & 31;
    const int m0 = (warp >> 1) << 4;
    const int n0 = (warp & 1) << 5;
    const int gr = lane >> 2;
    const int qc = (lane & 3) << 1;

    float d[4][4] = {};
#pragma unroll
    for (int seg = 0; seg < 3; ++seg) {
        const __nv_bfloat16* A = (seg < 2) ? sx0 : sx1;
        const __nv_bfloat16* Bm = (seg == 1) ? sw1 : sw0;
        const __nv_bfloat16* ar = A + (m0 + gr) * 264 + qc;
#pragma unroll 4
        for (int kk = 0; kk < 256; kk += 16) {
            unsigned a0 = *reinterpret_cast<const unsigned*>(ar + kk);
            unsigned a1 = *reinterpret_cast<const unsigned*>(ar + kk + 8 * 264);
            unsigned a2 = *reinterpret_cast<const unsigned*>(ar + kk + 8);
            unsigned a3 = *reinterpret_cast<const unsigned*>(ar + kk + 8 * 264 + 8);
#pragma unroll
            for (int nj = 0; nj < 4; ++nj) {
                const __nv_bfloat16* bp = Bm + (n0 + nj * 8 + gr) * 264 + kk + qc;
                unsigned b0 = *reinterpret_cast<const unsigned*>(bp);
                unsigned b1 = *reinterpret_cast<const unsigned*>(bp + 8);
                mma16816(d[nj][0], d[nj][1], d[nj][2], d[nj][3], a0, a1, a2, a3, b0, b1);
            }
        }
    }

    // transposed store: xp[t=mt][j][b]
    const int bb = m0 + gr;
    const int colg = nt * 64 + n0 + qc;
    float* outb = g_xp + (size_t)mt * (BB * HH);
#pragma unroll
    for (int nj = 0; nj < 4; ++nj) {
        int j = colg + nj * 8;
        float bsA = b_ih[j] + b_hh[j];
        float bsB = b_ih[j + 1] + b_hh[j + 1];
        outb[(size_t)j * 64 + bb] = d[nj][0] + bsA;
        outb[(size_t)(j + 1) * 64 + bb] = d[nj][1] + bsB;
        outb[(size_t)j * 64 + bb + 8] = d[nj][2] + bsA;
        outb[(size_t)(j + 1) * 64 + bb + 8] = d[nj][3] + bsB;
    }
}

// ---------------- phase 2: persistent scan, all-warp reduce + split named barrier ----------------
// R12 flag scheme (per-CTA fA/fB). Reduce runs on all 8 warps (2 floats/thread),
// warps 0-3 bar.arrive then poll fB + DMA; warps 4-7 bar.sync then publish fB.
__global__ void __launch_bounds__(256, 1) rnn_scan_kernel() {
    extern __shared__ __align__(16) unsigned char smem_raw[];
    const uint32_t sbase = smem_u32(smem_raw);
    const uint32_t uSH0 = sbase;            // 16KB swizzled h0 k-window
    const uint32_t uSH1 = sbase + 16384;    // 16KB swizzled h1 k-window
    __nv_bfloat16* sw0 = reinterpret_cast<__nv_bfloat16*>(smem_raw + 32768);   // 64 x 136
    __nv_bfloat16* sw1 = sw0 + 64 * 136;
    const uint32_t mbF = sbase + 67584;     // 4 quarter barriers

    const int tid = threadIdx.x;
    const int bid = blockIdx.x;
    const int nt = bid >> 3;
    const int ks = bid & 7;

    copy_tile<128, 136>(sw0, g_whh0 + (size_t)(nt * 64) * HH + ks * 128, HH);
    copy_tile<128, 136>(sw1, g_whh1 + (size_t)(nt * 64) * HH + ks * 128, HH);
    if (tid == 0) {
#pragma unroll
        for (int i = 0; i < 4; ++i)
            asm volatile("mbarrier.init.shared.b64 [%0], %1;"
                         ::"r"(mbF + i * 8), "r"(1u) : "memory");
    }
    __syncthreads();

    const int warp = tid >> 5, lane = tid & 31;
    const int m0 = (warp >> 1) << 4;   // j sub-tile
    const int n0 = (warp & 1) << 5;    // b half
    const int gr = lane >> 2;
    const int qc = (lane & 3) << 1;

    // hoist W fragments into registers for all 512 steps
    const uint32_t uW0 = smem_u32(sw0), uW1 = smem_u32(sw1);
    const uint32_t a_off = (uint32_t)((m0 + (lane & 15)) * 272 + (lane >> 4) * 16);
    unsigned W0f[8][4], W1f[8][4];
#pragma unroll
    for (int kk = 0; kk < 8; ++kk) {
        ldsm_x4(W0f[kk][0], W0f[kk][1], W0f[kk][2], W0f[kk][3], uW0 + a_off + kk * 32);
        ldsm_x4(W1f[kk][0], W1f[kk][1], W1f[kk][2], W1f[kk][3], uW1 + a_off + kk * 32);
    }

    // swizzled ldsm bases for h tiles (128B rows, SW128 XOR; constant per lane)
    const uint32_t raw1 = (uint32_t)((lane & 15) * 128 + (((lane >> 4) << 3) + n0) * 2);
    const uint32_t raw2 = raw1 + 32;
    const uint32_t hA = raw1 ^ ((raw1 >> 3) & 0x70);
    const uint32_t hB = raw2 ^ ((raw2 >> 3) & 0x70);

    unsigned* const fA_my = g_flagA + bid * 8;
    unsigned* const fB_my = g_flagB + bid * 8;
    const unsigned* const fBq =
        g_flagB + (size_t)(ks * 16 + (warp & 3) * 4 + (lane & 3)) * 8;
    const unsigned* const fAp = g_flagA + (nt * 8 + (lane & 7)) * 8;
    const int rbase = bid * 512 + tid * 2;   // reduce slice (all warps, 2 floats/thread)

    // ---- prologue: issue DMA for step 0 (flags trivially 0) ----
    if (warp < 4) {
        if (lane < 4) {
            while (ld_acq(fBq) != 0u) {}
        }
        __syncwarp();
        if (lane == 0) {
            const uint32_t mb = mbF + warp * 8;
            const uint32_t off = (uint32_t)(warp * 4096);
            const char* s0 = reinterpret_cast<const char*>(g_h0) + ks * 16384 + off;
            const char* s1 = reinterpret_cast<const char*>(g_h1) + ks * 16384 + off;
            asm volatile("mbarrier.arrive.expect_tx.shared.b64 _, [%0], %1;"
                         ::"r"(mb), "r"(8192u) : "memory");
            asm volatile(
                "cp.async.bulk.shared::cluster.global.mbarrier::complete_tx::bytes "
                "[%0], [%1], %2, [%3];"
                ::"r"(uSH0 + off), "l"(s0), "r"(4096u), "r"(mb) : "memory");
            asm volatile(
                "cp.async.bulk.shared::cluster.global.mbarrier::complete_tx::bytes "
                "[%0], [%1], %2, [%3];"
                ::"r"(uSH1 + off), "l"(s1), "r"(4096u), "r"(mb) : "memory");
        }
    }

    for (int t = 0; t < TT; ++t) {
        const unsigned p = (unsigned)(t & 1);

        // xp prefetch for reduce (all warps; 2 floats each, hidden behind MMA)
        float2 acc = *reinterpret_cast<const float2*>(g_xp + (size_t)t * (BB * HH) + rbase);

        // ---- MMA with progressive quarter waits: D += W0*h0 + W1*h0 + W0*h1 ----
        float d[4][4] = {};
#pragma unroll
        for (int kk = 0; kk < 8; ++kk) {
            if ((kk & 1) == 0) mbar_wait(mbF + (kk >> 1) * 8, p);
            unsigned r0, r1, r2, r3, s0, s1, s2, s3;
            ldsm_x4t(r0, r1, r2, r3, uSH0 + hA + kk * 2048);
            ldsm_x4t(s0, s1, s2, s3, uSH0 + hB + kk * 2048);
            mma16816(d[0][0], d[0][1], d[0][2], d[0][3],
                     W0f[kk][0], W0f[kk][1], W0f[kk][2], W0f[kk][3], r0, r1);
            mma16816(d[1][0], d[1][1], d[1][2], d[1][3],
                     W0f[kk][0], W0f[kk][1], W0f[kk][2], W0f[kk][3], r2, r3);
            mma16816(d[2][0], d[2][1], d[2][2], d[2][3],
                     W0f[kk][0], W0f[kk][1], W0f[kk][2], W0f[kk][3], s0, s1);
            mma16816(d[3][0], d[3][1], d[3][2], d[3][3],
                     W0f[kk][0], W0f[kk][1], W0f[kk][2], W0f[kk][3], s2, s3);
            mma16816(d[0][0], d[0][1], d[0][2], d[0][3],
                     W1f[kk][0], W1f[kk][1], W1f[kk][2], W1f[kk][3], r0, r1);
            mma16816(d[1][0], d[1][1], d[1][2], d[1][3],
                     W1f[kk][0], W1f[kk][1], W1f[kk][2], W1f[kk][3], r2, r3);
            mma16816(d[2][0], d[2][1], d[2][2], d[2][3],
                     W1f[kk][0], W1f[kk][1], W1f[kk][2], W1f[kk][3], s0, s1);
            mma16816(d[3][0], d[3][1], d[3][2], d[3][3],
                     W1f[kk][0], W1f[kk][1], W1f[kk][2], W1f[kk][3], s2, s3);
            unsigned u0, u1, u2, u3, v0, v1, v2, v3;
            ldsm_x4t(u0, u1, u2, u3, uSH1 + hA + kk * 2048);
            ldsm_x4t(v0, v1, v2, v3, uSH1 + hB + kk * 2048);
            mma16816(d[0][0], d[0][1], d[0][2], d[0][3],
                     W0f[kk][0], W0f[kk][1], W0f[kk][2], W0f[kk][3], u0, u1);
            mma16816(d[1][0], d[1][1], d[1][2], d[1][3],
                     W0f[kk][0], W0f[kk][1], W0f[kk][2], W0f[kk][3], u2, u3);
            mma16816(d[2][0], d[2][1], d[2][2], d[2][3],
                     W0f[kk][0], W0f[kk][1], W0f[kk][2], W0f[kk][3], v0, v1);
            mma16816(d[3][0], d[3][1], d[3][2], d[3][3],
                     W0f[kk][0], W0f[kk][1], W0f[kk][2], W0f[kk][3], v2, v3);
        }

        // ---- store partials [parity][ks][j][b] ----
        float* Pp = g_part + ((size_t)p * 8 + ks) * (BB * HH) +
                    (size_t)(nt * 64 + m0 + gr) * 64 + n0 + qc;
#pragma unroll
        for (int nj = 0; nj < 4; ++nj) {
            *reinterpret_cast<float2*>(Pp + nj * 8) = make_float2(d[nj][0], d[nj][1]);
            *reinterpret_cast<float2*>(Pp + nj * 8 + 8 * 64) = make_float2(d[nj][2], d[nj][3]);
        }
        __syncthreads();   // all MMA + ldsm + partial stores done (also WAR gate for DMA)
        if (tid == 0) st_rel(fA_my, p ^ 1u);

        // ---- warp 4 polls partner fA flags; block barrier releases everyone ----
        if (warp == 4 && lane < 8) {
            while (ld_acq(fAp) != (p ^ 1u)) {}
        }
        __syncthreads();

        // ---- reduce on ALL warps (2 floats/thread), tanh, split, store h_{t+1} ----
        {
            float sx = acc.x, sy = acc.y;
#pragma unroll
            for (int s = 0; s < 8; ++s) {
                float2 q = *reinterpret_cast<const float2*>(
                    g_part + ((size_t)p * 8 + s) * (BB * HH) + rbase);
                sx += q.x;
                sy += q.y;
            }
            float hx = ftanh(sx), hy = ftanh(sy);
            const int j = rbase >> 6, b0 = rbase & 63;
            uint32_t raw = (uint32_t)((j & 127) * 128 + b0 * 2);
            uint32_t boff = (uint32_t)(((t + 1) % 3) * 131072 + (j >> 7) * 16384) +
                            (raw ^ ((raw >> 3) & 0x70));
            __nv_bfloat162 v0;
            v0.x = __float2bfloat16(hx);
            v0.y = __float2bfloat16(hy);
            *reinterpret_cast<__nv_bfloat162*>(reinterpret_cast<char*>(g_h0) + boff) = v0;
            __nv_bfloat162 v1;
            v1.x = __float2bfloat16(hx - __bfloat162float(v0.x));
            v1.y = __float2bfloat16(hy - __bfloat162float(v0.y));
            *reinterpret_cast<__nv_bfloat162*>(reinterpret_cast<char*>(g_h1) + boff) = v1;
            if (t == TT - 1) {   // h_512 transposed [b][j] in f32
                g_hT[(size_t)b0 * HH + j] = hx;
                g_hT[(size_t)(b0 + 1) * HH + j] = hy;
            }
        }

        if (warp < 4) {
            // non-blocking arrival: h stores of warps 0-3 are counted, then go poll+DMA
            asm volatile("bar.arrive 3, 256;" ::: "memory");
            if (t < TT - 1) {
                const unsigned pn = (unsigned)((t + 1) & 1);
                if (lane < 4) {
                    while (ld_acq(fBq) != pn) {}
                }
                __syncwarp();
                if (lane == 0) {
                    const uint32_t mb = mbF + warp * 8;
                    const uint32_t off = (uint32_t)(warp * 4096);
                    const int tb = (t + 1) % 3;
                    const char* s0 =
                        reinterpret_cast<const char*>(g_h0) + tb * 131072 + ks * 16384 + off;
                    const char* s1 =
                        reinterpret_cast<const char*>(g_h1) + tb * 131072 + ks * 16384 + off;
                    asm volatile("mbarrier.arrive.expect_tx.shared.b64 _, [%0], %1;"
                                 ::"r"(mb), "r"(8192u) : "memory");
                    asm volatile(
                        "cp.async.bulk.shared::cluster.global.mbarrier::complete_tx::bytes "
                        "[%0], [%1], %2, [%3];"
                        ::"r"(uSH0 + off), "l"(s0), "r"(4096u), "r"(mb) : "memory");
                    asm volatile(
                        "cp.async.bulk.shared::cluster.global.mbarrier::complete_tx::bytes "
                        "[%0], [%1], %2, [%3];"
                        ::"r"(uSH1 + off), "l"(s1), "r"(4096u), "r"(mb) : "memory");
                }
            }
        } else {
            // blocking: wait all 256 h stores (128 arrivals + these 128), then publish
            asm volatile("bar.sync 3, 256;" ::: "memory");
            if (tid == 128) st_rel(fB_my, p ^ 1u);
        }
    }
}

// ---------------- phase 3: out = h_last @ W_lin^T + b_lin ----------------
__global__ void final_linear_kernel(const float* __restrict__ wlin,
                                    const float* __restrict__ blin,
                                    float* __restrict__ out) {
    int gw = (blockIdx.x * 256 + threadIdx.x) >> 5;
    int lane = threadIdx.x & 31;
    int b = gw >> 7;
    int o = gw & (OO - 1);
    const float* wr = wlin + (size_t)o * HH;
    const float* hr = g_hT + (size_t)b * HH;
    float sum = 0.0f;
#pragma unroll 8
    for (int k = lane; k < HH; k += 32) sum += hr[k] * wr[k];
#pragma unroll
    for (int off = 16; off > 0; off >>= 1) sum += __shfl_down_sync(0xffffffffu, sum, off);
    if (lane == 0) out[b * OO + o] = sum + blin[o];
}

// ---------------- launch ----------------
extern "C" void kernel_launch(void* const* d_in, const int* in_sizes, int n_in,
                              void* d_out, int out_size) {
    (void)in_sizes; (void)n_in; (void)out_size;
    const float* x     = (const float*)d_in[0];
    const float* W_ih  = (const float*)d_in[1];
    const float* W_hh  = (const float*)d_in[2];
    const float* b_ih  = (const float*)d_in[3];
    const float* b_hh  = (const float*)d_in[4];
    const float* W_lin = (const float*)d_in[5];
    const float* b_lin = (const float*)d_in[6];
    float* out = (float*)d_out;

    const int scan_smem = 67616;   // 32KB h + 34816B W + 4 mbarriers
    cudaFuncSetAttribute(xp_gemm_kernel, cudaFuncAttributeMaxDynamicSharedMemorySize,
                         4 * 64 * 264 * 2);
    cudaFuncSetAttribute(rnn_scan_kernel, cudaFuncAttributeMaxDynamicSharedMemorySize,
                         scan_smem);

    fused_prep_kernel<<<38144, 256>>>(x, W_ih, W_hh);                     // launch 1
    xp_gemm_kernel<<<dim3(512, 16), 256, 4 * 64 * 264 * 2>>>(b_ih, b_hh); // launch 2
    spacer_kernel<<<1, 32>>>();                                           // launch 3
    rnn_scan_kernel<<<NCTA, 256, scan_smem>>>();                          // launch 4 (ncu target)
    final_linear_kernel<<<(BB * OO * 32) / 256, 256>>>(W_lin, b_lin, out);
}